// round 6
// baseline (speedup 1.0000x reference)
#include <cuda_runtime.h>
#include <cuda_fp16.h>
#include <math.h>
#include <stdint.h>

#define BDIM 16
#define SEQ  1024
#define HIDN 768
#define NH   12
#define HD   64
#define NBH  (BDIM*NH)   // 192
#define XDP  384          // dpairs per hidden row
#define HDP  32           // dpairs per head row

// Split-fp16 scratch (u32 = half2). Allocation-free: __device__ globals.
__device__ uint32_t g_xh[(size_t)BDIM*SEQ*XDP], g_xl[(size_t)BDIM*SEQ*XDP];
__device__ uint32_t g_wh[(size_t)4*HIDN*XDP],   g_wl[(size_t)4*HIDN*XDP];   // Wq,Wk,Wv,Wo stacked
__device__ uint32_t g_qh[(size_t)NBH*SEQ*HDP],  g_ql[(size_t)NBH*SEQ*HDP];
__device__ uint32_t g_kh[(size_t)NBH*SEQ*HDP],  g_kl[(size_t)NBH*SEQ*HDP];
__device__ uint32_t g_vh[(size_t)NBH*SEQ*HDP],  g_vl[(size_t)NBH*SEQ*HDP];
__device__ uint32_t g_vth[(size_t)NBH*HD*(SEQ/2)], g_vtl[(size_t)NBH*HD*(SEQ/2)];
__device__ uint32_t g_oh[(size_t)NBH*SEQ*HDP],  g_ol[(size_t)NBH*SEQ*HDP];

// m16n8k16 fp16 MMA, fp32 accum. g=lane>>2, q=lane&3.
// A: a0=(g,2q:2q+1) a1=(g+8,..) a2=(g,2q+8:2q+9) a3=(g+8,..)
// B: b0=(k=2q:2q+1,n=g) b1=(k=2q+8:2q+9,n=g)
// C: c0=(g,2q) c1=(g,2q+1) c2=(g+8,2q) c3=(g+8,2q+1)
__device__ __forceinline__ void mma_f16(float c[4],
    uint32_t a0, uint32_t a1, uint32_t a2, uint32_t a3,
    uint32_t b0, uint32_t b1)
{
    asm volatile(
        "mma.sync.aligned.m16n8k16.row.col.f32.f16.f16.f32 "
        "{%0,%1,%2,%3},{%4,%5,%6,%7},{%8,%9},{%0,%1,%2,%3};\n"
        : "+f"(c[0]), "+f"(c[1]), "+f"(c[2]), "+f"(c[3])
        : "r"(a0), "r"(a1), "r"(a2), "r"(a3), "r"(b0), "r"(b1));
}

__device__ __forceinline__ uint32_t packh(__half a, __half b){
    __half2 h = __halves2half2(a, b);
    return *(uint32_t*)&h;
}
__device__ __forceinline__ void split_pair(float x, float y, uint32_t &hi, uint32_t &lo){
    __half hx = __float2half_rn(x);
    __half hy = __float2half_rn(y);
    __half lx = __float2half_rn(x - __half2float(hx));
    __half ly = __float2half_rn(y - __half2float(hy));
    hi = packh(hx, hy);
    lo = packh(lx, ly);
}

#define QS 20   // row stride (u32) for 16-dpair rows: (20g+q)%32 hits 32 banks
#define KS 36   // row stride (u32) for 32-dpair rows: (36g+q)%32 = (4g+q)%32

// ---------------------------------------------------------------------------
// Split conversion: which=0 -> x into g_xh/g_xl; which=1..4 -> W_i into g_wh/g_wl.
// One thread = one float4 = 2 dpairs.
// ---------------------------------------------------------------------------
__global__ __launch_bounds__(256) void split_conv(const float* __restrict__ src,
                                                  int which, int nf4)
{
    int i = blockIdx.x*blockDim.x + threadIdx.x;
    if (i >= nf4) return;
    uint32_t* oh; uint32_t* ol;
    if (which == 0){ oh = g_xh; ol = g_xl; }
    else { size_t off = (size_t)(which-1)*HIDN*XDP; oh = g_wh + off; ol = g_wl + off; }
    float4 v = ((const float4*)src)[i];
    uint32_t h0,l0,h1,l1;
    split_pair(v.x, v.y, h0, l0);
    split_pair(v.z, v.w, h1, l1);
    oh[2*i  ] = h0; oh[2*i+1] = h1;
    ol[2*i  ] = l0; ol[2*i+1] = l1;
}

// ---------------------------------------------------------------------------
// Fused QKV projection over the combined 2304-col space. grid=(128,18), 256 thr.
// BM=128, BN=128, BK=32 (16 dpairs). Warps 4(m) x 2(n), warp tile 32x64.
// Epilogue: bias + RoPE(+scale) and DIRECT split-u32 stores to g_{q,k,v}{h,l}.
// ---------------------------------------------------------------------------
__global__ __launch_bounds__(256) void qkv_kernel(
    const float* __restrict__ bq, const float* __restrict__ bk,
    const float* __restrict__ bv,
    const float* __restrict__ cosc, const float* __restrict__ sinc)
{
    __shared__ uint32_t xsh[128*QS], xsl[128*QS];
    __shared__ uint32_t wsh_[128*QS], wsl_[128*QS];

    const int row0 = blockIdx.x * 128;
    const int cb   = blockIdx.y;
    const int tid  = threadIdx.x;
    const int w    = tid >> 5, lane = tid & 31;
    const int g    = lane >> 2, q = lane & 3;
    const int warpm = w >> 1, warpn = w & 1;

    float c[2][8][4];
    #pragma unroll
    for (int mf=0; mf<2; mf++)
        #pragma unroll
        for (int nf=0; nf<8; nf++)
            #pragma unroll
            for (int e=0; e<4; e++) c[mf][nf][e]=0.f;

    const int lrow = tid >> 1;              // 0..127
    const int loff = (tid & 1) * 8;         // 0 or 8 (dpairs)

    for (int k0 = 0; k0 < XDP; k0 += 16) {
        const uint32_t* xh_p = g_xh + (size_t)(row0 + lrow)*XDP + k0 + loff;
        const uint32_t* xl_p = g_xl + (size_t)(row0 + lrow)*XDP + k0 + loff;
        const uint32_t* wh_p = g_wh + (size_t)(cb*128 + lrow)*XDP + k0 + loff;
        const uint32_t* wl_p = g_wl + (size_t)(cb*128 + lrow)*XDP + k0 + loff;
        uint4 a0 = *(const uint4*)(xh_p    );
        uint4 a1 = *(const uint4*)(xh_p + 4);
        uint4 a2 = *(const uint4*)(xl_p    );
        uint4 a3 = *(const uint4*)(xl_p + 4);
        uint4 b0 = *(const uint4*)(wh_p    );
        uint4 b1 = *(const uint4*)(wh_p + 4);
        uint4 b2 = *(const uint4*)(wl_p    );
        uint4 b3 = *(const uint4*)(wl_p + 4);
        __syncthreads();
        *(uint4*)&xsh[lrow*QS + loff    ] = a0;
        *(uint4*)&xsh[lrow*QS + loff + 4] = a1;
        *(uint4*)&xsl[lrow*QS + loff    ] = a2;
        *(uint4*)&xsl[lrow*QS + loff + 4] = a3;
        *(uint4*)&wsh_[lrow*QS + loff    ] = b0;
        *(uint4*)&wsh_[lrow*QS + loff + 4] = b1;
        *(uint4*)&wsl_[lrow*QS + loff    ] = b2;
        *(uint4*)&wsl_[lrow*QS + loff + 4] = b3;
        __syncthreads();
        #pragma unroll
        for (int kf=0; kf<2; kf++){
            uint32_t ah[2][4], al[2][4];
            #pragma unroll
            for (int mf=0; mf<2; mf++){
                int r = warpm*32 + mf*16 + g;
                ah[mf][0]=xsh[(r  )*QS + kf*8 + q  ]; ah[mf][1]=xsh[(r+8)*QS + kf*8 + q  ];
                ah[mf][2]=xsh[(r  )*QS + kf*8 + q+4]; ah[mf][3]=xsh[(r+8)*QS + kf*8 + q+4];
                al[mf][0]=xsl[(r  )*QS + kf*8 + q  ]; al[mf][1]=xsl[(r+8)*QS + kf*8 + q  ];
                al[mf][2]=xsl[(r  )*QS + kf*8 + q+4]; al[mf][3]=xsl[(r+8)*QS + kf*8 + q+4];
            }
            #pragma unroll
            for (int nf=0; nf<8; nf++){
                int n = warpn*64 + nf*8 + g;
                uint32_t bh0=wsh_[n*QS + kf*8 + q], bh1=wsh_[n*QS + kf*8 + q+4];
                uint32_t bl0=wsl_[n*QS + kf*8 + q], bl1=wsl_[n*QS + kf*8 + q+4];
                #pragma unroll
                for (int mf=0; mf<2; mf++){
                    mma_f16(c[mf][nf], ah[mf][0],ah[mf][1],ah[mf][2],ah[mf][3], bh0,bh1);
                    mma_f16(c[mf][nf], ah[mf][0],ah[mf][1],ah[mf][2],ah[mf][3], bl0,bl1);
                    mma_f16(c[mf][nf], al[mf][0],al[mf][1],al[mf][2],al[mf][3], bh0,bh1);
                }
            }
        }
        __syncthreads();
    }

    #pragma unroll
    for (int nf=0; nf<8; nf++){
        int gcol = cb*128 + warpn*64 + nf*8 + 2*q;   // even
        int z  = gcol / HIDN;
        int zc = gcol % HIDN;
        int h  = zc >> 6;
        int t  = (zc & 63) >> 1;                      // dpair within head
        const float* bp = (z==0) ? bq : (z==1) ? bk : bv;
        float b0 = bp[zc], b1 = bp[zc+1];
        uint32_t* oh = (z==0) ? g_qh : (z==1) ? g_kh : g_vh;
        uint32_t* ol = (z==0) ? g_ql : (z==1) ? g_kl : g_vl;
        const float sc = (z==0) ? 0.125f : 1.0f;
        #pragma unroll
        for (int mf=0; mf<2; mf++){
            #pragma unroll
            for (int half=0; half<2; half++){
                int row = row0 + warpm*32 + mf*16 + g + half*8;
                int b_ = row >> 10, s_ = row & 1023;
                float v0 = c[mf][nf][half*2+0] + b0;
                float v1 = c[mf][nf][half*2+1] + b1;
                if (z != 2){
                    float cs_ = cosc[s_*32 + t], sn_ = sinc[s_*32 + t];
                    float r0v = (v0*cs_ - v1*sn_)*sc;
                    float r1v = (v1*cs_ + v0*sn_)*sc;
                    v0 = r0v; v1 = r1v;
                }
                uint32_t hi, lo;
                split_pair(v0, v1, hi, lo);
                size_t idx = ((size_t)(b_*NH + h)*SEQ + s_)*HDP + t;
                oh[idx] = hi; ol[idx] = lo;
            }
        }
    }
}

// ---------------------------------------------------------------------------
// V transpose (u32 byte-perm only): g_v[key][dpair] -> g_vt[d][keypair].
// grid = (16, 192): block = (64-key slab, bh). 256 threads.
// ---------------------------------------------------------------------------
__global__ __launch_bounds__(256) void vtrans_kernel()
{
    __shared__ uint32_t sh[64*KS], sl[64*KS];
    const int bh   = blockIdx.y;
    const int key0 = blockIdx.x * 64;
    const int tid  = threadIdx.x;

    {
        int r1 = tid >> 3,      o1 = (tid & 7) * 4;
        int r2 = r1 + 32;
        const uint32_t* ph = g_vh + ((size_t)bh*SEQ + key0)*HDP;
        const uint32_t* pl = g_vl + ((size_t)bh*SEQ + key0)*HDP;
        *(uint4*)&sh[r1*KS + o1] = *(const uint4*)(ph + (size_t)r1*HDP + o1);
        *(uint4*)&sh[r2*KS + o1] = *(const uint4*)(ph + (size_t)r2*HDP + o1);
        *(uint4*)&sl[r1*KS + o1] = *(const uint4*)(pl + (size_t)r1*HDP + o1);
        *(uint4*)&sl[r2*KS + o1] = *(const uint4*)(pl + (size_t)r2*HDP + o1);
    }
    __syncthreads();

    const int d   = tid >> 2;          // 0..63
    const int kb  = (tid & 3) * 8;     // local keypair base
    const int dp  = d >> 1;
    const uint32_t sel = (d & 1) ? 0x7632u : 0x5410u;
    uint32_t outh[8], outl[8];
    #pragma unroll
    for (int l=0; l<8; l++){
        int lk = kb + l;
        outh[l] = __byte_perm(sh[(2*lk)*KS + dp], sh[(2*lk+1)*KS + dp], sel);
        outl[l] = __byte_perm(sl[(2*lk)*KS + dp], sl[(2*lk+1)*KS + dp], sel);
    }
    uint32_t* dsth = g_vth + ((size_t)bh*HD + d)*(SEQ/2) + key0/2 + kb;
    uint32_t* dstl = g_vtl + ((size_t)bh*HD + d)*(SEQ/2) + key0/2 + kb;
    #pragma unroll
    for (int l=0; l<8; l+=4){
        *(uint4*)(dsth + l) = make_uint4(outh[l],outh[l+1],outh[l+2],outh[l+3]);
        *(uint4*)(dstl + l) = make_uint4(outl[l],outl[l+1],outl[l+2],outl[l+3]);
    }
}

// ---------------------------------------------------------------------------
// RSE attention (split-fp16, preconverted operands). CTA = 128 query rows of
// one (b,h), 8 warps; warp owns 16 rows. Sequential scan over 32 key blocks.
// ---------------------------------------------------------------------------
__global__ __launch_bounds__(256) void attn_kernel(const float* __restrict__ lam_p)
{
    __shared__ uint32_t kh[32*KS],  kl[32*KS];     // K [key][dpair]
    __shared__ uint32_t vth[64*QS], vtl[64*QS];    // V^T [d][keypair]
    __shared__ uint32_t wsh[128*QS], wsl[128*QS];  // w [row][keypair]

    const int bh = blockIdx.y;
    const int m0 = blockIdx.x * 128;
    const int tid = threadIdx.x;
    const int w = tid >> 5, lane = tid & 31;
    const int g = lane >> 2, q = lane & 3;
    const float lam = *lam_p;

    // Q fragments direct from split global
    uint32_t qah[4][4], qal[4][4];
    {
        const uint32_t* ph = g_qh + ((size_t)bh*SEQ + m0 + 16*w)*HDP;
        const uint32_t* pl = g_ql + ((size_t)bh*SEQ + m0 + 16*w)*HDP;
        #pragma unroll
        for (int kf=0; kf<4; kf++){
            qah[kf][0] = ph[(size_t)(g  )*HDP + kf*8 + q  ];
            qah[kf][1] = ph[(size_t)(g+8)*HDP + kf*8 + q  ];
            qah[kf][2] = ph[(size_t)(g  )*HDP + kf*8 + q+4];
            qah[kf][3] = ph[(size_t)(g+8)*HDP + kf*8 + q+4];
            qal[kf][0] = pl[(size_t)(g  )*HDP + kf*8 + q  ];
            qal[kf][1] = pl[(size_t)(g+8)*HDP + kf*8 + q  ];
            qal[kf][2] = pl[(size_t)(g  )*HDP + kf*8 + q+4];
            qal[kf][3] = pl[(size_t)(g+8)*HDP + kf*8 + q+4];
        }
    }

    float rem0=1.f, rem1=1.f, li0=0.f, li1=0.f, mi0=-INFINITY, mi1=-INFINITY;
    float acc[8][4];
    #pragma unroll
    for (int nf=0; nf<8; nf++)
        #pragma unroll
        for (int e=0; e<4; e++) acc[nf][e]=0.f;

    const float sq0 = (float)(m0 + 16*w + g);
    const float sq1 = sq0 + 8.f;
    const int rw0 = 16*w + g;

    const int krow = tid >> 3, koff = (tid & 7) * 4;   // K tile: 32x32 dp
    const int vrow = tid >> 2, voff = (tid & 3) * 4;   // V^T tile: 64x16 kp

    for (int nb=0; nb<32; nb++){
        const uint32_t* kph = g_kh + ((size_t)bh*SEQ + nb*32)*HDP;
        const uint32_t* kpl = g_kl + ((size_t)bh*SEQ + nb*32)*HDP;
        const uint32_t* vph = g_vth + (size_t)bh*HD*(SEQ/2) + nb*16;
        const uint32_t* vpl = g_vtl + (size_t)bh*HD*(SEQ/2) + nb*16;
        uint4 t0 = *(const uint4*)(kph + (size_t)krow*HDP + koff);
        uint4 t1 = *(const uint4*)(kpl + (size_t)krow*HDP + koff);
        uint4 t2 = *(const uint4*)(vph + (size_t)vrow*(SEQ/2) + voff);
        uint4 t3 = *(const uint4*)(vpl + (size_t)vrow*(SEQ/2) + voff);
        __syncthreads();
        *(uint4*)&kh[krow*KS + koff]  = t0;
        *(uint4*)&kl[krow*KS + koff]  = t1;
        *(uint4*)&vth[vrow*QS + voff] = t2;
        *(uint4*)&vtl[vrow*QS + voff] = t3;
        __syncthreads();

        // QK^T: 16 x 32, k=64 (4 k16 steps x 3 split-MMAs)
        float cf[4][4];
        #pragma unroll
        for (int nf=0; nf<4; nf++){
            #pragma unroll
            for (int e=0; e<4; e++) cf[nf][e]=0.f;
            int n = nf*8 + g;
            #pragma unroll
            for (int kf=0; kf<4; kf++){
                uint32_t b0h = kh[n*KS + kf*8 + q], b1h = kh[n*KS + kf*8 + q+4];
                uint32_t b0l = kl[n*KS + kf*8 + q], b1l = kl[n*KS + kf*8 + q+4];
                mma_f16(cf[nf], qah[kf][0],qah[kf][1],qah[kf][2],qah[kf][3], b0h,b1h);
                mma_f16(cf[nf], qah[kf][0],qah[kf][1],qah[kf][2],qah[kf][3], b0l,b1l);
                mma_f16(cf[nf], qal[kf][0],qal[kf][1],qal[kf][2],qal[kf][3], b0h,b1h);
            }
        }

        // Pointwise: decay, sigmoid, w = rem * beta; split w into hi/lo
        float sw0=0.f, sw1=0.f, mx0=-INFINITY, mx1=-INFINITY;
        #pragma unroll
        for (int nf=0; nf<4; nf++){
            int colk = nf*8 + 2*q;
            float sk0 = (float)(nb*32 + colk);
            float sk1 = sk0 + 1.f;
            {
                float raw0 = cf[nf][0] - lam*fabsf(sq0 - sk0);
                float raw1 = cf[nf][1] - lam*fabsf(sq0 - sk1);
                mx0 = fmaxf(mx0, fmaxf(raw0, raw1));
                float cl0 = fminf(fmaxf(raw0, -20.f), 20.f);
                float cl1 = fminf(fmaxf(raw1, -20.f), 20.f);
                float w0 = rem0 / (1.f + __expf(-cl0));
                float w1 = rem0 / (1.f + __expf(-cl1));
                sw0 += w0 + w1;
                uint32_t hi, lo;
                split_pair(w0, w1, hi, lo);
                wsh[rw0*QS + nf*4 + q] = hi;
                wsl[rw0*QS + nf*4 + q] = lo;
            }
            {
                float raw0 = cf[nf][2] - lam*fabsf(sq1 - sk0);
                float raw1 = cf[nf][3] - lam*fabsf(sq1 - sk1);
                mx1 = fmaxf(mx1, fmaxf(raw0, raw1));
                float cl0 = fminf(fmaxf(raw0, -20.f), 20.f);
                float cl1 = fminf(fmaxf(raw1, -20.f), 20.f);
                float w0 = rem1 / (1.f + __expf(-cl0));
                float w1 = rem1 / (1.f + __expf(-cl1));
                sw1 += w0 + w1;
                uint32_t hi, lo;
                split_pair(w0, w1, hi, lo);
                wsh[(rw0+8)*QS + nf*4 + q] = hi;
                wsl[(rw0+8)*QS + nf*4 + q] = lo;
            }
        }
        #pragma unroll
        for (int ofs=2; ofs>0; ofs>>=1){
            sw0 += __shfl_xor_sync(0xffffffffu, sw0, ofs);
            sw1 += __shfl_xor_sync(0xffffffffu, sw1, ofs);
            mx0  = fmaxf(mx0, __shfl_xor_sync(0xffffffffu, mx0, ofs));
            mx1  = fmaxf(mx1, __shfl_xor_sync(0xffffffffu, mx1, ofs));
        }
        {
            float mn = fmaxf(mi0, mx0);
            li0 = li0*exp2f(mi0-mn) + sw0; mi0 = mn;
            rem0 = fmaxf(rem0*(1.f - sw0), 1e-6f);
        }
        {
            float mn = fmaxf(mi1, mx1);
            li1 = li1*exp2f(mi1-mn) + sw1; mi1 = mn;
            rem1 = fmaxf(rem1*(1.f - sw1), 1e-6f);
        }
        __syncwarp();

        // PV: acc(16 x 64) += w(16 x 32keys) @ V(32keys x 64)
        #pragma unroll
        for (int kf=0; kf<2; kf++){
            uint32_t a0h = wsh[(rw0  )*QS + kf*8 + q  ];
            uint32_t a1h = wsh[(rw0+8)*QS + kf*8 + q  ];
            uint32_t a2h = wsh[(rw0  )*QS + kf*8 + q+4];
            uint32_t a3h = wsh[(rw0+8)*QS + kf*8 + q+4];
            uint32_t a0l = wsl[(rw0  )*QS + kf*8 + q  ];
            uint32_t a1l = wsl[(rw0+8)*QS + kf*8 + q  ];
            uint32_t a2l = wsl[(rw0  )*QS + kf*8 + q+4];
            uint32_t a3l = wsl[(rw0+8)*QS + kf*8 + q+4];
            #pragma unroll
            for (int nf=0; nf<8; nf++){
                int n = nf*8 + g;
                uint32_t b0h = vth[n*QS + kf*8 + q], b1h = vth[n*QS + kf*8 + q+4];
                uint32_t b0l = vtl[n*QS + kf*8 + q], b1l = vtl[n*QS + kf*8 + q+4];
                mma_f16(acc[nf], a0h,a1h,a2h,a3h, b0h,b1h);
                mma_f16(acc[nf], a0h,a1h,a2h,a3h, b0l,b1l);
                mma_f16(acc[nf], a0l,a1l,a2l,a3l, b0h,b1h);
            }
        }
    }

    // Epilogue: normalize and store split O
    const float inv0 = 1.f / fmaxf(li0, 1e-6f);
    const float inv1 = 1.f / fmaxf(li1, 1e-6f);
    uint32_t* poh = g_oh + ((size_t)bh*SEQ + m0 + 16*w)*HDP;
    uint32_t* pol = g_ol + ((size_t)bh*SEQ + m0 + 16*w)*HDP;
    #pragma unroll
    for (int nf=0; nf<8; nf++){
        int dp = nf*4 + q;
        uint32_t hi, lo;
        split_pair(acc[nf][0]*inv0, acc[nf][1]*inv0, hi, lo);
        poh[(size_t)(g  )*HDP + dp] = hi; pol[(size_t)(g  )*HDP + dp] = lo;
        split_pair(acc[nf][2]*inv1, acc[nf][3]*inv1, hi, lo);
        poh[(size_t)(g+8)*HDP + dp] = hi; pol[(size_t)(g+8)*HDP + dp] = lo;
    }
}

// ---------------------------------------------------------------------------
// Output projection: y = ctx @ Wo^T + bo. grid=(128,6), 256 threads.
// ctx gathered from split g_o; Wo from rows 2304.. of g_w.
// ---------------------------------------------------------------------------
__global__ __launch_bounds__(256) void out_kernel(
    const float* __restrict__ bo, float* __restrict__ y)
{
    __shared__ uint32_t xsh[128*QS], xsl[128*QS];
    __shared__ uint32_t wsh_[128*QS], wsl_[128*QS];

    const int row0 = blockIdx.x * 128;
    const int cb   = blockIdx.y;
    const int tid  = threadIdx.x;
    const int w    = tid >> 5, lane = tid & 31;
    const int g    = lane >> 2, q = lane & 3;
    const int warpm = w >> 1, warpn = w & 1;

    float c[2][8][4];
    #pragma unroll
    for (int mf=0; mf<2; mf++)
        #pragma unroll
        for (int nf=0; nf<8; nf++)
            #pragma unroll
            for (int e=0; e<4; e++) c[mf][nf][e]=0.f;

    const int lrow = tid >> 1;
    const int loff = (tid & 1) * 8;
    const int grow = row0 + lrow;
    const int b_l = grow >> 10, s_l = grow & 1023;

    for (int k0 = 0; k0 < XDP; k0 += 16) {
        uint4 a[2][2], b[2][2];
        #pragma unroll
        for (int cth=0; cth<2; cth++){
            int kdp = k0 + loff + cth*4;
            int hh = kdp >> 5, dph = kdp & 31;
            size_t xi = ((size_t)(b_l*NH + hh)*SEQ + s_l)*HDP + dph;
            a[cth][0] = *(const uint4*)(g_oh + xi);
            a[cth][1] = *(const uint4*)(g_ol + xi);
            size_t wi = (size_t)(3*HIDN + cb*128 + lrow)*XDP + kdp;
            b[cth][0] = *(const uint4*)(g_wh + wi);
            b[cth][1] = *(const uint4*)(g_wl + wi);
        }
        __syncthreads();
        #pragma unroll
        for (int cth=0; cth<2; cth++){
            *(uint4*)&xsh[lrow*QS + loff + cth*4]  = a[cth][0];
            *(uint4*)&xsl[lrow*QS + loff + cth*4]  = a[cth][1];
            *(uint4*)&wsh_[lrow*QS + loff + cth*4] = b[cth][0];
            *(uint4*)&wsl_[lrow*QS + loff + cth*4] = b[cth][1];
        }
        __syncthreads();
        #pragma unroll
        for (int kf=0; kf<2; kf++){
            uint32_t ah[2][4], al[2][4];
            #pragma unroll
            for (int mf=0; mf<2; mf++){
                int r = warpm*32 + mf*16 + g;
                ah[mf][0]=xsh[(r  )*QS + kf*8 + q  ]; ah[mf][1]=xsh[(r+8)*QS + kf*8 + q  ];
                ah[mf][2]=xsh[(r  )*QS + kf*8 + q+4]; ah[mf][3]=xsh[(r+8)*QS + kf*8 + q+4];
                al[mf][0]=xsl[(r  )*QS + kf*8 + q  ]; al[mf][1]=xsl[(r+8)*QS + kf*8 + q  ];
                al[mf][2]=xsl[(r  )*QS + kf*8 + q+4]; al[mf][3]=xsl[(r+8)*QS + kf*8 + q+4];
            }
            #pragma unroll
            for (int nf=0; nf<8; nf++){
                int n = warpn*64 + nf*8 + g;
                uint32_t bh0=wsh_[n*QS + kf*8 + q], bh1=wsh_[n*QS + kf*8 + q+4];
                uint32_t bl0=wsl_[n*QS + kf*8 + q], bl1=wsl_[n*QS + kf*8 + q+4];
                #pragma unroll
                for (int mf=0; mf<2; mf++){
                    mma_f16(c[mf][nf], ah[mf][0],ah[mf][1],ah[mf][2],ah[mf][3], bh0,bh1);
                    mma_f16(c[mf][nf], ah[mf][0],ah[mf][1],ah[mf][2],ah[mf][3], bl0,bl1);
                    mma_f16(c[mf][nf], al[mf][0],al[mf][1],al[mf][2],al[mf][3], bh0,bh1);
                }
            }
        }
        __syncthreads();
    }

    #pragma unroll
    for (int nf=0; nf<8; nf++){
        int col = cb*128 + warpn*64 + nf*8 + 2*q;
        float b0 = bo[col], b1 = bo[col+1];
        #pragma unroll
        for (int mf=0; mf<2; mf++){
            #pragma unroll
            for (int half=0; half<2; half++){
                int row = row0 + warpm*32 + mf*16 + g + half*8;
                *(float2*)(y + (size_t)row*HIDN + col) =
                    make_float2(c[mf][nf][half*2+0] + b0,
                                c[mf][nf][half*2+1] + b1);
            }
        }
    }
}

// ---------------------------------------------------------------------------
extern "C" void kernel_launch(void* const* d_in, const int* in_sizes, int n_in,
                              void* d_out, int out_size)
{
    const float* x    = (const float*)d_in[0];
    const float* Wq   = (const float*)d_in[1];
    const float* bq   = (const float*)d_in[2];
    const float* Wk   = (const float*)d_in[3];
    const float* bk   = (const float*)d_in[4];
    const float* Wv   = (const float*)d_in[5];
    const float* bv   = (const float*)d_in[6];
    const float* Wo   = (const float*)d_in[7];
    const float* bo   = (const float*)d_in[8];
    const float* lam  = (const float*)d_in[9];
    const float* cosc = (const float*)d_in[10];
    const float* sinc = (const float*)d_in[11];
    float* y = (float*)d_out;

    const int nf4_x = BDIM*SEQ*HIDN/4;       // 3145728
    const int nf4_w = HIDN*HIDN/4;           // 147456
    split_conv<<<(nf4_x+255)/256, 256>>>(x,  0, nf4_x);
    split_conv<<<(nf4_w+255)/256, 256>>>(Wq, 1, nf4_w);
    split_conv<<<(nf4_w+255)/256, 256>>>(Wk, 2, nf4_w);
    split_conv<<<(nf4_w+255)/256, 256>>>(Wv, 3, nf4_w);
    split_conv<<<(nf4_w+255)/256, 256>>>(Wo, 4, nf4_w);

    dim3 g1(BDIM*SEQ/128, 18);
    qkv_kernel<<<g1, 256>>>(bq, bk, bv, cosc, sinc);

    dim3 gt(SEQ/64, NBH);
    vtrans_kernel<<<gt, 256>>>();

    dim3 g2(SEQ/128, NBH);
    attn_kernel<<<g2, 256>>>(lam);

    dim3 g3(BDIM*SEQ/128, 6);
    out_kernel<<<g3, 256>>>(bo, y);
}

// round 7
// speedup vs baseline: 1.0046x; 1.0046x over previous
#include <cuda_runtime.h>
#include <cuda_fp16.h>
#include <math.h>
#include <stdint.h>

#define BDIM 16
#define SEQ  1024
#define HIDN 768
#define NH   12
#define HD   64
#define NBH  (BDIM*NH)   // 192
#define XDP  384          // dpairs per hidden row
#define HDP  32           // dpairs per head row

// Split-fp16 scratch (u32 = half2). Allocation-free: __device__ globals.
__device__ uint32_t g_xh[(size_t)BDIM*SEQ*XDP], g_xl[(size_t)BDIM*SEQ*XDP];
__device__ uint32_t g_wh[(size_t)4*HIDN*XDP],   g_wl[(size_t)4*HIDN*XDP];   // Wq,Wk,Wv,Wo stacked
__device__ uint32_t g_qh[(size_t)NBH*SEQ*HDP],  g_ql[(size_t)NBH*SEQ*HDP];
__device__ uint32_t g_kh[(size_t)NBH*SEQ*HDP],  g_kl[(size_t)NBH*SEQ*HDP];
__device__ uint32_t g_vh[(size_t)NBH*SEQ*HDP],  g_vl[(size_t)NBH*SEQ*HDP];
__device__ uint32_t g_vth[(size_t)NBH*HD*(SEQ/2)], g_vtl[(size_t)NBH*HD*(SEQ/2)];
__device__ uint32_t g_oh[(size_t)NBH*SEQ*HDP],  g_ol[(size_t)NBH*SEQ*HDP];

// m16n8k16 fp16 MMA, fp32 accum. g=lane>>2, q=lane&3.
__device__ __forceinline__ void mma_f16(float c[4],
    uint32_t a0, uint32_t a1, uint32_t a2, uint32_t a3,
    uint32_t b0, uint32_t b1)
{
    asm volatile(
        "mma.sync.aligned.m16n8k16.row.col.f32.f16.f16.f32 "
        "{%0,%1,%2,%3},{%4,%5,%6,%7},{%8,%9},{%0,%1,%2,%3};\n"
        : "+f"(c[0]), "+f"(c[1]), "+f"(c[2]), "+f"(c[3])
        : "r"(a0), "r"(a1), "r"(a2), "r"(a3), "r"(b0), "r"(b1));
}

__device__ __forceinline__ uint32_t packh(__half a, __half b){
    __half2 h = __halves2half2(a, b);
    return *(uint32_t*)&h;
}
__device__ __forceinline__ void split_pair(float x, float y, uint32_t &hi, uint32_t &lo){
    __half hx = __float2half_rn(x);
    __half hy = __float2half_rn(y);
    __half lx = __float2half_rn(x - __half2float(hx));
    __half ly = __float2half_rn(y - __half2float(hy));
    hi = packh(hx, hy);
    lo = packh(lx, ly);
}

#define QS 20   // row stride (u32) for 16-dpair rows
#define KS 36   // row stride (u32) for 32-dpair rows

// ---------------------------------------------------------------------------
// Split conversion: which=0 -> x; which=1..4 -> W_i. One thread = one float4.
// ---------------------------------------------------------------------------
__global__ __launch_bounds__(256) void split_conv(const float* __restrict__ src,
                                                  int which, int nf4)
{
    int i = blockIdx.x*blockDim.x + threadIdx.x;
    if (i >= nf4) return;
    uint32_t* oh; uint32_t* ol;
    if (which == 0){ oh = g_xh; ol = g_xl; }
    else { size_t off = (size_t)(which-1)*HIDN*XDP; oh = g_wh + off; ol = g_wl + off; }
    float4 v = ((const float4*)src)[i];
    uint32_t h0,l0,h1,l1;
    split_pair(v.x, v.y, h0, l0);
    split_pair(v.z, v.w, h1, l1);
    oh[2*i  ] = h0; oh[2*i+1] = h1;
    ol[2*i  ] = l0; ol[2*i+1] = l1;
}

// ---------------------------------------------------------------------------
// Fused QKV projection. grid=(128,12,3), 256 thr. BM=128, BN=64, BK=32.
// Warps 4(m) x 2(n), warp tile 32x32, c[2][4][4] (round-5 register profile).
// Reads pre-split x/W; epilogue: bias + RoPE(+scale), split-u32 stores.
// ---------------------------------------------------------------------------
__global__ __launch_bounds__(256) void qkv_kernel(
    const float* __restrict__ bq, const float* __restrict__ bk,
    const float* __restrict__ bv,
    const float* __restrict__ cosc, const float* __restrict__ sinc)
{
    __shared__ uint32_t xsh[128*QS], xsl[128*QS];
    __shared__ uint32_t wsh_[64*QS], wsl_[64*QS];

    const int z    = blockIdx.z;
    const int h    = blockIdx.y;
    const int row0 = blockIdx.x * 128;
    const int tid  = threadIdx.x;
    const int w    = tid >> 5, lane = tid & 31;
    const int g    = lane >> 2, q = lane & 3;
    const int warpm = w >> 1, warpn = w & 1;

    const uint32_t* wbh = g_wh + (size_t)z*HIDN*XDP + (size_t)h*64*XDP;
    const uint32_t* wbl = g_wl + (size_t)z*HIDN*XDP + (size_t)h*64*XDP;
    const float* bias = (z==0) ? bq : (z==1) ? bk : bv;
    uint32_t* ohp = (z==0) ? g_qh : (z==1) ? g_kh : g_vh;
    uint32_t* olp = (z==0) ? g_ql : (z==1) ? g_kl : g_vl;
    const float sc = (z==0) ? 0.125f : 1.0f;

    float c[2][4][4];
    #pragma unroll
    for (int mf=0; mf<2; mf++)
        #pragma unroll
        for (int nf=0; nf<4; nf++)
            #pragma unroll
            for (int e=0; e<4; e++) c[mf][nf][e]=0.f;

    const int lrow = tid >> 1, loff = (tid & 1) * 8;   // x loader: 128x16dp
    const int wrow = tid >> 2, woff = (tid & 3) * 4;   // W loader: 64x16dp

    for (int k0 = 0; k0 < XDP; k0 += 16) {
        const uint32_t* xh_p = g_xh + (size_t)(row0 + lrow)*XDP + k0 + loff;
        const uint32_t* xl_p = g_xl + (size_t)(row0 + lrow)*XDP + k0 + loff;
        uint4 a0 = *(const uint4*)(xh_p    );
        uint4 a1 = *(const uint4*)(xh_p + 4);
        uint4 a2 = *(const uint4*)(xl_p    );
        uint4 a3 = *(const uint4*)(xl_p + 4);
        uint4 b0 = *(const uint4*)(wbh + (size_t)wrow*XDP + k0 + woff);
        uint4 b1 = *(const uint4*)(wbl + (size_t)wrow*XDP + k0 + woff);
        __syncthreads();
        *(uint4*)&xsh[lrow*QS + loff    ] = a0;
        *(uint4*)&xsh[lrow*QS + loff + 4] = a1;
        *(uint4*)&xsl[lrow*QS + loff    ] = a2;
        *(uint4*)&xsl[lrow*QS + loff + 4] = a3;
        *(uint4*)&wsh_[wrow*QS + woff] = b0;
        *(uint4*)&wsl_[wrow*QS + woff] = b1;
        __syncthreads();
        #pragma unroll
        for (int kf=0; kf<2; kf++){
            uint32_t ah[2][4], al[2][4];
            #pragma unroll
            for (int mf=0; mf<2; mf++){
                int r = warpm*32 + mf*16 + g;
                ah[mf][0]=xsh[(r  )*QS + kf*8 + q  ]; ah[mf][1]=xsh[(r+8)*QS + kf*8 + q  ];
                ah[mf][2]=xsh[(r  )*QS + kf*8 + q+4]; ah[mf][3]=xsh[(r+8)*QS + kf*8 + q+4];
                al[mf][0]=xsl[(r  )*QS + kf*8 + q  ]; al[mf][1]=xsl[(r+8)*QS + kf*8 + q  ];
                al[mf][2]=xsl[(r  )*QS + kf*8 + q+4]; al[mf][3]=xsl[(r+8)*QS + kf*8 + q+4];
            }
            #pragma unroll
            for (int nf=0; nf<4; nf++){
                int n = warpn*32 + nf*8 + g;
                uint32_t bh0=wsh_[n*QS + kf*8 + q], bh1=wsh_[n*QS + kf*8 + q+4];
                uint32_t bl0=wsl_[n*QS + kf*8 + q], bl1=wsl_[n*QS + kf*8 + q+4];
                #pragma unroll
                for (int mf=0; mf<2; mf++){
                    mma_f16(c[mf][nf], ah[mf][0],ah[mf][1],ah[mf][2],ah[mf][3], bh0,bh1);
                    mma_f16(c[mf][nf], ah[mf][0],ah[mf][1],ah[mf][2],ah[mf][3], bl0,bl1);
                    mma_f16(c[mf][nf], al[mf][0],al[mf][1],al[mf][2],al[mf][3], bh0,bh1);
                }
            }
        }
        __syncthreads();
    }

    #pragma unroll
    for (int nf=0; nf<4; nf++){
        int col = warpn*32 + nf*8 + 2*q;      // even, 0..62 within head
        float b0 = bias[h*64 + col], b1 = bias[h*64 + col + 1];
        int t = col >> 1;                      // dpair index within head
        #pragma unroll
        for (int mf=0; mf<2; mf++){
            #pragma unroll
            for (int half=0; half<2; half++){
                int row = row0 + warpm*32 + mf*16 + g + half*8;
                int b_ = row >> 10, s_ = row & 1023;
                float v0 = c[mf][nf][half*2+0] + b0;
                float v1 = c[mf][nf][half*2+1] + b1;
                if (z != 2){
                    float cs_ = cosc[s_*32 + t], sn_ = sinc[s_*32 + t];
                    float r0v = (v0*cs_ - v1*sn_)*sc;
                    float r1v = (v1*cs_ + v0*sn_)*sc;
                    v0 = r0v; v1 = r1v;
                }
                uint32_t hi, lo;
                split_pair(v0, v1, hi, lo);
                size_t idx = ((size_t)(b_*NH + h)*SEQ + s_)*HDP + t;
                ohp[idx] = hi; olp[idx] = lo;
            }
        }
    }
}

// ---------------------------------------------------------------------------
// V transpose (u32 byte-perm only): g_v[key][dpair] -> g_vt[d][keypair].
// grid = (16, 192). 256 threads.
// ---------------------------------------------------------------------------
__global__ __launch_bounds__(256) void vtrans_kernel()
{
    __shared__ uint32_t sh[64*KS], sl[64*KS];
    const int bh   = blockIdx.y;
    const int key0 = blockIdx.x * 64;
    const int tid  = threadIdx.x;

    {
        int r1 = tid >> 3,      o1 = (tid & 7) * 4;
        int r2 = r1 + 32;
        const uint32_t* ph = g_vh + ((size_t)bh*SEQ + key0)*HDP;
        const uint32_t* pl = g_vl + ((size_t)bh*SEQ + key0)*HDP;
        *(uint4*)&sh[r1*KS + o1] = *(const uint4*)(ph + (size_t)r1*HDP + o1);
        *(uint4*)&sh[r2*KS + o1] = *(const uint4*)(ph + (size_t)r2*HDP + o1);
        *(uint4*)&sl[r1*KS + o1] = *(const uint4*)(pl + (size_t)r1*HDP + o1);
        *(uint4*)&sl[r2*KS + o1] = *(const uint4*)(pl + (size_t)r2*HDP + o1);
    }
    __syncthreads();

    const int d   = tid >> 2;          // 0..63
    const int kb  = (tid & 3) * 8;     // local keypair base
    const int dp  = d >> 1;
    const uint32_t sel = (d & 1) ? 0x7632u : 0x5410u;
    uint32_t outh[8], outl[8];
    #pragma unroll
    for (int l=0; l<8; l++){
        int lk = kb + l;
        outh[l] = __byte_perm(sh[(2*lk)*KS + dp], sh[(2*lk+1)*KS + dp], sel);
        outl[l] = __byte_perm(sl[(2*lk)*KS + dp], sl[(2*lk+1)*KS + dp], sel);
    }
    uint32_t* dsth = g_vth + ((size_t)bh*HD + d)*(SEQ/2) + key0/2 + kb;
    uint32_t* dstl = g_vtl + ((size_t)bh*HD + d)*(SEQ/2) + key0/2 + kb;
    #pragma unroll
    for (int l=0; l<8; l+=4){
        *(uint4*)(dsth + l) = make_uint4(outh[l],outh[l+1],outh[l+2],outh[l+3]);
        *(uint4*)(dstl + l) = make_uint4(outl[l],outl[l+1],outl[l+2],outl[l+3]);
    }
}

// ---------------------------------------------------------------------------
// RSE attention (split-fp16, preconverted operands). CTA = 128 query rows of
// one (b,h), 8 warps; warp owns 16 rows. Sequential scan over 32 key blocks.
// ---------------------------------------------------------------------------
__global__ __launch_bounds__(256) void attn_kernel(const float* __restrict__ lam_p)
{
    __shared__ uint32_t kh[32*KS],  kl[32*KS];     // K [key][dpair]
    __shared__ uint32_t vth[64*QS], vtl[64*QS];    // V^T [d][keypair]
    __shared__ uint32_t wsh[128*QS], wsl[128*QS];  // w [row][keypair]

    const int bh = blockIdx.y;
    const int m0 = blockIdx.x * 128;
    const int tid = threadIdx.x;
    const int w = tid >> 5, lane = tid & 31;
    const int g = lane >> 2, q = lane & 3;
    const float lam = *lam_p;

    // Q fragments direct from split global
    uint32_t qah[4][4], qal[4][4];
    {
        const uint32_t* ph = g_qh + ((size_t)bh*SEQ + m0 + 16*w)*HDP;
        const uint32_t* pl = g_ql + ((size_t)bh*SEQ + m0 + 16*w)*HDP;
        #pragma unroll
        for (int kf=0; kf<4; kf++){
            qah[kf][0] = ph[(size_t)(g  )*HDP + kf*8 + q  ];
            qah[kf][1] = ph[(size_t)(g+8)*HDP + kf*8 + q  ];
            qah[kf][2] = ph[(size_t)(g  )*HDP + kf*8 + q+4];
            qah[kf][3] = ph[(size_t)(g+8)*HDP + kf*8 + q+4];
            qal[kf][0] = pl[(size_t)(g  )*HDP + kf*8 + q  ];
            qal[kf][1] = pl[(size_t)(g+8)*HDP + kf*8 + q  ];
            qal[kf][2] = pl[(size_t)(g  )*HDP + kf*8 + q+4];
            qal[kf][3] = pl[(size_t)(g+8)*HDP + kf*8 + q+4];
        }
    }

    float rem0=1.f, rem1=1.f, li0=0.f, li1=0.f, mi0=-INFINITY, mi1=-INFINITY;
    float acc[8][4];
    #pragma unroll
    for (int nf=0; nf<8; nf++)
        #pragma unroll
        for (int e=0; e<4; e++) acc[nf][e]=0.f;

    const float sq0 = (float)(m0 + 16*w + g);
    const float sq1 = sq0 + 8.f;
    const int rw0 = 16*w + g;

    const int krow = tid >> 3, koff = (tid & 7) * 4;   // K tile: 32x32 dp
    const int vrow = tid >> 2, voff = (tid & 3) * 4;   // V^T tile: 64x16 kp

    for (int nb=0; nb<32; nb++){
        const uint32_t* kph = g_kh + ((size_t)bh*SEQ + nb*32)*HDP;
        const uint32_t* kpl = g_kl + ((size_t)bh*SEQ + nb*32)*HDP;
        const uint32_t* vph = g_vth + (size_t)bh*HD*(SEQ/2) + nb*16;
        const uint32_t* vpl = g_vtl + (size_t)bh*HD*(SEQ/2) + nb*16;
        uint4 t0 = *(const uint4*)(kph + (size_t)krow*HDP + koff);
        uint4 t1 = *(const uint4*)(kpl + (size_t)krow*HDP + koff);
        uint4 t2 = *(const uint4*)(vph + (size_t)vrow*(SEQ/2) + voff);
        uint4 t3 = *(const uint4*)(vpl + (size_t)vrow*(SEQ/2) + voff);
        __syncthreads();
        *(uint4*)&kh[krow*KS + koff]  = t0;
        *(uint4*)&kl[krow*KS + koff]  = t1;
        *(uint4*)&vth[vrow*QS + voff] = t2;
        *(uint4*)&vtl[vrow*QS + voff] = t3;
        __syncthreads();

        // QK^T: 16 x 32, k=64 (4 k16 steps x 3 split-MMAs)
        float cf[4][4];
        #pragma unroll
        for (int nf=0; nf<4; nf++){
            #pragma unroll
            for (int e=0; e<4; e++) cf[nf][e]=0.f;
            int n = nf*8 + g;
            #pragma unroll
            for (int kf=0; kf<4; kf++){
                uint32_t b0h = kh[n*KS + kf*8 + q], b1h = kh[n*KS + kf*8 + q+4];
                uint32_t b0l = kl[n*KS + kf*8 + q], b1l = kl[n*KS + kf*8 + q+4];
                mma_f16(cf[nf], qah[kf][0],qah[kf][1],qah[kf][2],qah[kf][3], b0h,b1h);
                mma_f16(cf[nf], qah[kf][0],qah[kf][1],qah[kf][2],qah[kf][3], b0l,b1l);
                mma_f16(cf[nf], qal[kf][0],qal[kf][1],qal[kf][2],qal[kf][3], b0h,b1h);
            }
        }

        // Pointwise: decay, sigmoid, w = rem * beta; split w into hi/lo
        float sw0=0.f, sw1=0.f, mx0=-INFINITY, mx1=-INFINITY;
        #pragma unroll
        for (int nf=0; nf<4; nf++){
            int colk = nf*8 + 2*q;
            float sk0 = (float)(nb*32 + colk);
            float sk1 = sk0 + 1.f;
            {
                float raw0 = cf[nf][0] - lam*fabsf(sq0 - sk0);
                float raw1 = cf[nf][1] - lam*fabsf(sq0 - sk1);
                mx0 = fmaxf(mx0, fmaxf(raw0, raw1));
                float cl0 = fminf(fmaxf(raw0, -20.f), 20.f);
                float cl1 = fminf(fmaxf(raw1, -20.f), 20.f);
                float w0 = rem0 / (1.f + __expf(-cl0));
                float w1 = rem0 / (1.f + __expf(-cl1));
                sw0 += w0 + w1;
                uint32_t hi, lo;
                split_pair(w0, w1, hi, lo);
                wsh[rw0*QS + nf*4 + q] = hi;
                wsl[rw0*QS + nf*4 + q] = lo;
            }
            {
                float raw0 = cf[nf][2] - lam*fabsf(sq1 - sk0);
                float raw1 = cf[nf][3] - lam*fabsf(sq1 - sk1);
                mx1 = fmaxf(mx1, fmaxf(raw0, raw1));
                float cl0 = fminf(fmaxf(raw0, -20.f), 20.f);
                float cl1 = fminf(fmaxf(raw1, -20.f), 20.f);
                float w0 = rem1 / (1.f + __expf(-cl0));
                float w1 = rem1 / (1.f + __expf(-cl1));
                sw1 += w0 + w1;
                uint32_t hi, lo;
                split_pair(w0, w1, hi, lo);
                wsh[(rw0+8)*QS + nf*4 + q] = hi;
                wsl[(rw0+8)*QS + nf*4 + q] = lo;
            }
        }
        #pragma unroll
        for (int ofs=2; ofs>0; ofs>>=1){
            sw0 += __shfl_xor_sync(0xffffffffu, sw0, ofs);
            sw1 += __shfl_xor_sync(0xffffffffu, sw1, ofs);
            mx0  = fmaxf(mx0, __shfl_xor_sync(0xffffffffu, mx0, ofs));
            mx1  = fmaxf(mx1, __shfl_xor_sync(0xffffffffu, mx1, ofs));
        }
        {
            float mn = fmaxf(mi0, mx0);
            li0 = li0*exp2f(mi0-mn) + sw0; mi0 = mn;
            rem0 = fmaxf(rem0*(1.f - sw0), 1e-6f);
        }
        {
            float mn = fmaxf(mi1, mx1);
            li1 = li1*exp2f(mi1-mn) + sw1; mi1 = mn;
            rem1 = fmaxf(rem1*(1.f - sw1), 1e-6f);
        }
        __syncwarp();

        // PV: acc(16 x 64) += w(16 x 32keys) @ V(32keys x 64)
        #pragma unroll
        for (int kf=0; kf<2; kf++){
            uint32_t a0h = wsh[(rw0  )*QS + kf*8 + q  ];
            uint32_t a1h = wsh[(rw0+8)*QS + kf*8 + q  ];
            uint32_t a2h = wsh[(rw0  )*QS + kf*8 + q+4];
            uint32_t a3h = wsh[(rw0+8)*QS + kf*8 + q+4];
            uint32_t a0l = wsl[(rw0  )*QS + kf*8 + q  ];
            uint32_t a1l = wsl[(rw0+8)*QS + kf*8 + q  ];
            uint32_t a2l = wsl[(rw0  )*QS + kf*8 + q+4];
            uint32_t a3l = wsl[(rw0+8)*QS + kf*8 + q+4];
            #pragma unroll
            for (int nf=0; nf<8; nf++){
                int n = nf*8 + g;
                uint32_t b0h = vth[n*QS + kf*8 + q], b1h = vth[n*QS + kf*8 + q+4];
                uint32_t b0l = vtl[n*QS + kf*8 + q], b1l = vtl[n*QS + kf*8 + q+4];
                mma_f16(acc[nf], a0h,a1h,a2h,a3h, b0h,b1h);
                mma_f16(acc[nf], a0h,a1h,a2h,a3h, b0l,b1l);
                mma_f16(acc[nf], a0l,a1l,a2l,a3l, b0h,b1h);
            }
        }
    }

    // Epilogue: normalize and store split O
    const float inv0 = 1.f / fmaxf(li0, 1e-6f);
    const float inv1 = 1.f / fmaxf(li1, 1e-6f);
    uint32_t* poh = g_oh + ((size_t)bh*SEQ + m0 + 16*w)*HDP;
    uint32_t* pol = g_ol + ((size_t)bh*SEQ + m0 + 16*w)*HDP;
    #pragma unroll
    for (int nf=0; nf<8; nf++){
        int dp = nf*4 + q;
        uint32_t hi, lo;
        split_pair(acc[nf][0]*inv0, acc[nf][1]*inv0, hi, lo);
        poh[(size_t)(g  )*HDP + dp] = hi; pol[(size_t)(g  )*HDP + dp] = lo;
        split_pair(acc[nf][2]*inv1, acc[nf][3]*inv1, hi, lo);
        poh[(size_t)(g+8)*HDP + dp] = hi; pol[(size_t)(g+8)*HDP + dp] = lo;
    }
}

// ---------------------------------------------------------------------------
// Output projection: y = ctx @ Wo^T + bo. grid=(128,12), 256 threads.
// BM=128, BN=64, warp tile 32x32 (round-5 register profile), split operands.
// ---------------------------------------------------------------------------
__global__ __launch_bounds__(256) void out_kernel(
    const float* __restrict__ bo, float* __restrict__ y)
{
    __shared__ uint32_t xsh[128*QS], xsl[128*QS];
    __shared__ uint32_t wsh_[64*QS], wsl_[64*QS];

    const int row0 = blockIdx.x * 128;
    const int cb   = blockIdx.y;
    const int tid  = threadIdx.x;
    const int w    = tid >> 5, lane = tid & 31;
    const int g    = lane >> 2, q = lane & 3;
    const int warpm = w >> 1, warpn = w & 1;

    float c[2][4][4];
    #pragma unroll
    for (int mf=0; mf<2; mf++)
        #pragma unroll
        for (int nf=0; nf<4; nf++)
            #pragma unroll
            for (int e=0; e<4; e++) c[mf][nf][e]=0.f;

    const int lrow = tid >> 1, loff = (tid & 1) * 8;
    const int wrow = tid >> 2, woff = (tid & 3) * 4;
    const int grow = row0 + lrow;
    const int b_l = grow >> 10, s_l = grow & 1023;
    const uint32_t* wbh = g_wh + (size_t)(3*HIDN + cb*64)*XDP;
    const uint32_t* wbl = g_wl + (size_t)(3*HIDN + cb*64)*XDP;

    for (int k0 = 0; k0 < XDP; k0 += 16) {
        uint4 a[2][2];
        #pragma unroll
        for (int cth=0; cth<2; cth++){
            int kdp = k0 + loff + cth*4;
            int hh = kdp >> 5, dph = kdp & 31;
            size_t xi = ((size_t)(b_l*NH + hh)*SEQ + s_l)*HDP + dph;
            a[cth][0] = *(const uint4*)(g_oh + xi);
            a[cth][1] = *(const uint4*)(g_ol + xi);
        }
        uint4 b0 = *(const uint4*)(wbh + (size_t)wrow*XDP + k0 + woff);
        uint4 b1 = *(const uint4*)(wbl + (size_t)wrow*XDP + k0 + woff);
        __syncthreads();
        #pragma unroll
        for (int cth=0; cth<2; cth++){
            *(uint4*)&xsh[lrow*QS + loff + cth*4] = a[cth][0];
            *(uint4*)&xsl[lrow*QS + loff + cth*4] = a[cth][1];
        }
        *(uint4*)&wsh_[wrow*QS + woff] = b0;
        *(uint4*)&wsl_[wrow*QS + woff] = b1;
        __syncthreads();
        #pragma unroll
        for (int kf=0; kf<2; kf++){
            uint32_t ah[2][4], al[2][4];
            #pragma unroll
            for (int mf=0; mf<2; mf++){
                int r = warpm*32 + mf*16 + g;
                ah[mf][0]=xsh[(r  )*QS + kf*8 + q  ]; ah[mf][1]=xsh[(r+8)*QS + kf*8 + q  ];
                ah[mf][2]=xsh[(r  )*QS + kf*8 + q+4]; ah[mf][3]=xsh[(r+8)*QS + kf*8 + q+4];
                al[mf][0]=xsl[(r  )*QS + kf*8 + q  ]; al[mf][1]=xsl[(r+8)*QS + kf*8 + q  ];
                al[mf][2]=xsl[(r  )*QS + kf*8 + q+4]; al[mf][3]=xsl[(r+8)*QS + kf*8 + q+4];
            }
            #pragma unroll
            for (int nf=0; nf<4; nf++){
                int n = warpn*32 + nf*8 + g;
                uint32_t bh0=wsh_[n*QS + kf*8 + q], bh1=wsh_[n*QS + kf*8 + q+4];
                uint32_t bl0=wsl_[n*QS + kf*8 + q], bl1=wsl_[n*QS + kf*8 + q+4];
                #pragma unroll
                for (int mf=0; mf<2; mf++){
                    mma_f16(c[mf][nf], ah[mf][0],ah[mf][1],ah[mf][2],ah[mf][3], bh0,bh1);
                    mma_f16(c[mf][nf], ah[mf][0],ah[mf][1],ah[mf][2],ah[mf][3], bl0,bl1);
                    mma_f16(c[mf][nf], al[mf][0],al[mf][1],al[mf][2],al[mf][3], bh0,bh1);
                }
            }
        }
        __syncthreads();
    }

    #pragma unroll
    for (int nf=0; nf<4; nf++){
        int col = cb*64 + warpn*32 + nf*8 + 2*q;
        float b0 = bo[col], b1 = bo[col+1];
        #pragma unroll
        for (int mf=0; mf<2; mf++){
            #pragma unroll
            for (int half=0; half<2; half++){
                int row = row0 + warpm*32 + mf*16 + g + half*8;
                *(float2*)(y + (size_t)row*HIDN + col) =
                    make_float2(c[mf][nf][half*2+0] + b0,
                                c[mf][nf][half*2+1] + b1);
            }
        }
    }
}

// ---------------------------------------------------------------------------
extern "C" void kernel_launch(void* const* d_in, const int* in_sizes, int n_in,
                              void* d_out, int out_size)
{
    const float* x    = (const float*)d_in[0];
    const float* Wq   = (const float*)d_in[1];
    const float* bq   = (const float*)d_in[2];
    const float* Wk   = (const float*)d_in[3];
    const float* bk   = (const float*)d_in[4];
    const float* Wv   = (const float*)d_in[5];
    const float* bv   = (const float*)d_in[6];
    const float* Wo   = (const float*)d_in[7];
    const float* bo   = (const float*)d_in[8];
    const float* lam  = (const float*)d_in[9];
    const float* cosc = (const float*)d_in[10];
    const float* sinc = (const float*)d_in[11];
    float* y = (float*)d_out;

    const int nf4_x = BDIM*SEQ*HIDN/4;
    const int nf4_w = HIDN*HIDN/4;
    split_conv<<<(nf4_x+255)/256, 256>>>(x,  0, nf4_x);
    split_conv<<<(nf4_w+255)/256, 256>>>(Wq, 1, nf4_w);
    split_conv<<<(nf4_w+255)/256, 256>>>(Wk, 2, nf4_w);
    split_conv<<<(nf4_w+255)/256, 256>>>(Wv, 3, nf4_w);
    split_conv<<<(nf4_w+255)/256, 256>>>(Wo, 4, nf4_w);

    dim3 g1(BDIM*SEQ/128, NH, 3);
    qkv_kernel<<<g1, 256>>>(bq, bk, bv, cosc, sinc);

    dim3 gt(SEQ/64, NBH);
    vtrans_kernel<<<gt, 256>>>();

    dim3 g2(SEQ/128, NBH);
    attn_kernel<<<g2, 256>>>(lam);

    dim3 g3(BDIM*SEQ/128, NH);
    out_kernel<<<g3, 256>>>(bo, y);
}

// round 8
// speedup vs baseline: 1.0943x; 1.0893x over previous
#include <cuda_runtime.h>
#include <cuda_fp16.h>
#include <math.h>
#include <stdint.h>

#define BDIM 16
#define SEQ  1024
#define HIDN 768
#define NH   12
#define HD   64
#define NBH  (BDIM*NH)   // 192
#define XDP  384          // dpairs per hidden row
#define HDP  32           // dpairs per head row

// Split-fp16 scratch (u32 = half2). Allocation-free: __device__ globals.
__device__ uint32_t g_xh[(size_t)BDIM*SEQ*XDP], g_xl[(size_t)BDIM*SEQ*XDP];
__device__ uint32_t g_wh[(size_t)4*HIDN*XDP],   g_wl[(size_t)4*HIDN*XDP];
__device__ uint32_t g_qh[(size_t)NBH*SEQ*HDP],  g_ql[(size_t)NBH*SEQ*HDP];
__device__ uint32_t g_kh[(size_t)NBH*SEQ*HDP],  g_kl[(size_t)NBH*SEQ*HDP];
__device__ uint32_t g_vh[(size_t)NBH*SEQ*HDP],  g_vl[(size_t)NBH*SEQ*HDP];
__device__ uint32_t g_vth[(size_t)NBH*HD*(SEQ/2)], g_vtl[(size_t)NBH*HD*(SEQ/2)];
__device__ uint32_t g_oh[(size_t)NBH*SEQ*HDP],  g_ol[(size_t)NBH*SEQ*HDP];

__device__ __forceinline__ void mma_f16(float c[4],
    uint32_t a0, uint32_t a1, uint32_t a2, uint32_t a3,
    uint32_t b0, uint32_t b1)
{
    asm volatile(
        "mma.sync.aligned.m16n8k16.row.col.f32.f16.f16.f32 "
        "{%0,%1,%2,%3},{%4,%5,%6,%7},{%8,%9},{%0,%1,%2,%3};\n"
        : "+f"(c[0]), "+f"(c[1]), "+f"(c[2]), "+f"(c[3])
        : "r"(a0), "r"(a1), "r"(a2), "r"(a3), "r"(b0), "r"(b1));
}

__device__ __forceinline__ uint32_t packh(__half a, __half b){
    __half2 h = __halves2half2(a, b);
    return *(uint32_t*)&h;
}
__device__ __forceinline__ void split_pair(float x, float y, uint32_t &hi, uint32_t &lo){
    __half hx = __float2half_rn(x);
    __half hy = __float2half_rn(y);
    __half lx = __float2half_rn(x - __half2float(hx));
    __half ly = __float2half_rn(y - __half2float(hy));
    hi = packh(hx, hy);
    lo = packh(lx, ly);
}

__device__ __forceinline__ uint32_t smaddr(const void* p){
    return (uint32_t)__cvta_generic_to_shared(p);
}
__device__ __forceinline__ void cp16(uint32_t s, const void* g){
    asm volatile("cp.async.cg.shared.global [%0], [%1], 16;\n" :: "r"(s), "l"(g));
}
#define CP_WAIT_ALL() asm volatile("cp.async.commit_group;\ncp.async.wait_group 0;\n" ::: "memory")

#define QS 20   // stride for 16-dpair rows (w tile)
#define KS 36   // stride for 32-dpair rows: (4g+q)%32 is a perfect permutation

// ---------------------------------------------------------------------------
// Split conversion: which=0 -> x; which=1..4 -> W_i. One thread = one float4.
// ---------------------------------------------------------------------------
__global__ __launch_bounds__(256) void split_conv(const float* __restrict__ src,
                                                  int which, int nf4)
{
    int i = blockIdx.x*blockDim.x + threadIdx.x;
    if (i >= nf4) return;
    uint32_t* oh; uint32_t* ol;
    if (which == 0){ oh = g_xh; ol = g_xl; }
    else { size_t off = (size_t)(which-1)*HIDN*XDP; oh = g_wh + off; ol = g_wl + off; }
    float4 v = ((const float4*)src)[i];
    uint32_t h0,l0,h1,l1;
    split_pair(v.x, v.y, h0, l0);
    split_pair(v.z, v.w, h1, l1);
    oh[2*i  ] = h0; oh[2*i+1] = h1;
    ol[2*i  ] = l0; ol[2*i+1] = l1;
}

// ---------------------------------------------------------------------------
// Fused QKV projection. grid=(128,12,3), 256 thr. BM=128, BN=64, BK=32dp.
// cp.async tile loads (full 128B rows). Warp tile 32x32, c[2][4][4].
// ---------------------------------------------------------------------------
#define QKV_SMEM ((128*KS*2 + 64*KS*2)*4)
__global__ __launch_bounds__(256) void qkv_kernel(
    const float* __restrict__ bq, const float* __restrict__ bk,
    const float* __restrict__ bv,
    const float* __restrict__ cosc, const float* __restrict__ sinc)
{
    extern __shared__ uint32_t smem[];
    uint32_t* xsh  = smem;               // 128*KS
    uint32_t* xsl  = xsh  + 128*KS;
    uint32_t* wsh_ = xsl  + 128*KS;      // 64*KS
    uint32_t* wsl_ = wsh_ + 64*KS;

    const int z    = blockIdx.z;
    const int h    = blockIdx.y;
    const int row0 = blockIdx.x * 128;
    const int tid  = threadIdx.x;
    const int w    = tid >> 5, lane = tid & 31;
    const int g    = lane >> 2, q = lane & 3;
    const int warpm = w >> 1, warpn = w & 1;

    const uint32_t* wbh = g_wh + (size_t)z*HIDN*XDP + (size_t)h*64*XDP;
    const uint32_t* wbl = g_wl + (size_t)z*HIDN*XDP + (size_t)h*64*XDP;
    const float* bias = (z==0) ? bq : (z==1) ? bk : bv;
    uint32_t* ohp = (z==0) ? g_qh : (z==1) ? g_kh : g_vh;
    uint32_t* olp = (z==0) ? g_ql : (z==1) ? g_kl : g_vl;
    const float sc = (z==0) ? 0.125f : 1.0f;

    float c[2][4][4];
    #pragma unroll
    for (int mf=0; mf<2; mf++)
        #pragma unroll
        for (int nf=0; nf<4; nf++)
            #pragma unroll
            for (int e=0; e<4; e++) c[mf][nf][e]=0.f;

    const int lrow = tid >> 3;            // 0..31
    const int koff = (tid & 7) * 4;       // 0..28 u32

    for (int k0 = 0; k0 < XDP; k0 += 32) {
        __syncthreads();
        #pragma unroll
        for (int i=0; i<4; i++){
            int r = lrow + 32*i;
            cp16(smaddr(&xsh[r*KS + koff]), g_xh + (size_t)(row0+r)*XDP + k0 + koff);
            cp16(smaddr(&xsl[r*KS + koff]), g_xl + (size_t)(row0+r)*XDP + k0 + koff);
        }
        #pragma unroll
        for (int i=0; i<2; i++){
            int r = lrow + 32*i;
            cp16(smaddr(&wsh_[r*KS + koff]), wbh + (size_t)r*XDP + k0 + koff);
            cp16(smaddr(&wsl_[r*KS + koff]), wbl + (size_t)r*XDP + k0 + koff);
        }
        CP_WAIT_ALL();
        __syncthreads();
        #pragma unroll
        for (int kf=0; kf<4; kf++){
            uint32_t ah[2][4], al[2][4];
            #pragma unroll
            for (int mf=0; mf<2; mf++){
                int r = warpm*32 + mf*16 + g;
                ah[mf][0]=xsh[(r  )*KS + kf*8 + q  ]; ah[mf][1]=xsh[(r+8)*KS + kf*8 + q  ];
                ah[mf][2]=xsh[(r  )*KS + kf*8 + q+4]; ah[mf][3]=xsh[(r+8)*KS + kf*8 + q+4];
                al[mf][0]=xsl[(r  )*KS + kf*8 + q  ]; al[mf][1]=xsl[(r+8)*KS + kf*8 + q  ];
                al[mf][2]=xsl[(r  )*KS + kf*8 + q+4]; al[mf][3]=xsl[(r+8)*KS + kf*8 + q+4];
            }
            #pragma unroll
            for (int nf=0; nf<4; nf++){
                int n = warpn*32 + nf*8 + g;
                uint32_t bh0=wsh_[n*KS + kf*8 + q], bh1=wsh_[n*KS + kf*8 + q+4];
                uint32_t bl0=wsl_[n*KS + kf*8 + q], bl1=wsl_[n*KS + kf*8 + q+4];
                #pragma unroll
                for (int mf=0; mf<2; mf++){
                    mma_f16(c[mf][nf], ah[mf][0],ah[mf][1],ah[mf][2],ah[mf][3], bh0,bh1);
                    mma_f16(c[mf][nf], ah[mf][0],ah[mf][1],ah[mf][2],ah[mf][3], bl0,bl1);
                    mma_f16(c[mf][nf], al[mf][0],al[mf][1],al[mf][2],al[mf][3], bh0,bh1);
                }
            }
        }
    }

    #pragma unroll
    for (int nf=0; nf<4; nf++){
        int col = warpn*32 + nf*8 + 2*q;
        float b0 = bias[h*64 + col], b1 = bias[h*64 + col + 1];
        int t = col >> 1;
        #pragma unroll
        for (int mf=0; mf<2; mf++){
            #pragma unroll
            for (int half=0; half<2; half++){
                int row = row0 + warpm*32 + mf*16 + g + half*8;
                int b_ = row >> 10, s_ = row & 1023;
                float v0 = c[mf][nf][half*2+0] + b0;
                float v1 = c[mf][nf][half*2+1] + b1;
                if (z != 2){
                    float cs_ = cosc[s_*32 + t], sn_ = sinc[s_*32 + t];
                    float r0v = (v0*cs_ - v1*sn_)*sc;
                    float r1v = (v1*cs_ + v0*sn_)*sc;
                    v0 = r0v; v1 = r1v;
                }
                uint32_t hi, lo;
                split_pair(v0, v1, hi, lo);
                size_t idx = ((size_t)(b_*NH + h)*SEQ + s_)*HDP + t;
                ohp[idx] = hi; olp[idx] = lo;
            }
        }
    }
}

// ---------------------------------------------------------------------------
// V transpose (u32 byte-perm only): g_v[key][dpair] -> g_vt[d][keypair].
// grid = (16, 192). 256 threads.
// ---------------------------------------------------------------------------
__global__ __launch_bounds__(256) void vtrans_kernel()
{
    __shared__ uint32_t sh[64*KS], sl[64*KS];
    const int bh   = blockIdx.y;
    const int key0 = blockIdx.x * 64;
    const int tid  = threadIdx.x;

    {
        int r1 = tid >> 3,      o1 = (tid & 7) * 4;
        int r2 = r1 + 32;
        const uint32_t* ph = g_vh + ((size_t)bh*SEQ + key0)*HDP;
        const uint32_t* pl = g_vl + ((size_t)bh*SEQ + key0)*HDP;
        *(uint4*)&sh[r1*KS + o1] = *(const uint4*)(ph + (size_t)r1*HDP + o1);
        *(uint4*)&sh[r2*KS + o1] = *(const uint4*)(ph + (size_t)r2*HDP + o1);
        *(uint4*)&sl[r1*KS + o1] = *(const uint4*)(pl + (size_t)r1*HDP + o1);
        *(uint4*)&sl[r2*KS + o1] = *(const uint4*)(pl + (size_t)r2*HDP + o1);
    }
    __syncthreads();

    const int d   = tid >> 2;          // 0..63
    const int kb  = (tid & 3) * 8;     // local keypair base
    const int dp  = d >> 1;
    const uint32_t sel = (d & 1) ? 0x7632u : 0x5410u;
    uint32_t outh[8], outl[8];
    #pragma unroll
    for (int l=0; l<8; l++){
        int lk = kb + l;
        outh[l] = __byte_perm(sh[(2*lk)*KS + dp], sh[(2*lk+1)*KS + dp], sel);
        outl[l] = __byte_perm(sl[(2*lk)*KS + dp], sl[(2*lk+1)*KS + dp], sel);
    }
    uint32_t* dsth = g_vth + ((size_t)bh*HD + d)*(SEQ/2) + key0/2 + kb;
    uint32_t* dstl = g_vtl + ((size_t)bh*HD + d)*(SEQ/2) + key0/2 + kb;
    #pragma unroll
    for (int l=0; l<8; l+=4){
        *(uint4*)(dsth + l) = make_uint4(outh[l],outh[l+1],outh[l+2],outh[l+3]);
        *(uint4*)(dstl + l) = make_uint4(outl[l],outl[l+1],outl[l+2],outl[l+3]);
    }
}

// ---------------------------------------------------------------------------
// RSE attention. CTA = 128 query rows of one (b,h), 8 warps. 2 key blocks
// (64 keys) loaded per sync via cp.async (128B rows); recurrence unchanged.
// ---------------------------------------------------------------------------
#define ATTN_SMEM ((64*KS*4 + 128*QS*2)*4)
__global__ __launch_bounds__(256) void attn_kernel(const float* __restrict__ lam_p)
{
    extern __shared__ uint32_t smem[];
    uint32_t* kh  = smem;              // 64*KS  (64 keys x 32 dp)
    uint32_t* kl  = kh  + 64*KS;
    uint32_t* vth = kl  + 64*KS;       // 64*KS  (64 d x 32 kp)
    uint32_t* vtl = vth + 64*KS;
    uint32_t* wsh = vtl + 64*KS;       // 128*QS (128 rows x 16 kp)
    uint32_t* wsl = wsh + 128*QS;

    const int bh = blockIdx.y;
    const int m0 = blockIdx.x * 128;
    const int tid = threadIdx.x;
    const int w = tid >> 5, lane = tid & 31;
    const int g = lane >> 2, q = lane & 3;
    const float lam = *lam_p;

    // Q fragments direct from split global
    uint32_t qah[4][4], qal[4][4];
    {
        const uint32_t* ph = g_qh + ((size_t)bh*SEQ + m0 + 16*w)*HDP;
        const uint32_t* pl = g_ql + ((size_t)bh*SEQ + m0 + 16*w)*HDP;
        #pragma unroll
        for (int kf=0; kf<4; kf++){
            qah[kf][0] = ph[(size_t)(g  )*HDP + kf*8 + q  ];
            qah[kf][1] = ph[(size_t)(g+8)*HDP + kf*8 + q  ];
            qah[kf][2] = ph[(size_t)(g  )*HDP + kf*8 + q+4];
            qah[kf][3] = ph[(size_t)(g+8)*HDP + kf*8 + q+4];
            qal[kf][0] = pl[(size_t)(g  )*HDP + kf*8 + q  ];
            qal[kf][1] = pl[(size_t)(g+8)*HDP + kf*8 + q  ];
            qal[kf][2] = pl[(size_t)(g  )*HDP + kf*8 + q+4];
            qal[kf][3] = pl[(size_t)(g+8)*HDP + kf*8 + q+4];
        }
    }

    float rem0=1.f, rem1=1.f, li0=0.f, li1=0.f, mi0=-INFINITY, mi1=-INFINITY;
    float acc[8][4];
    #pragma unroll
    for (int nf=0; nf<8; nf++)
        #pragma unroll
        for (int e=0; e<4; e++) acc[nf][e]=0.f;

    const float sq0 = (float)(m0 + 16*w + g);
    const float sq1 = sq0 + 8.f;
    const int rw0 = 16*w + g;

    const int lrow = tid >> 3;            // 0..31
    const int koff = (tid & 7) * 4;       // 0..28

    for (int nb2=0; nb2<16; nb2++){
        __syncthreads();
        const uint32_t* kph = g_kh + ((size_t)bh*SEQ + nb2*64)*HDP;
        const uint32_t* kpl = g_kl + ((size_t)bh*SEQ + nb2*64)*HDP;
        const uint32_t* vph = g_vth + (size_t)bh*HD*(SEQ/2) + nb2*32;
        const uint32_t* vpl = g_vtl + (size_t)bh*HD*(SEQ/2) + nb2*32;
        #pragma unroll
        for (int i=0; i<2; i++){
            int r = lrow + 32*i;
            cp16(smaddr(&kh[r*KS + koff]),  kph + (size_t)r*HDP + koff);
            cp16(smaddr(&kl[r*KS + koff]),  kpl + (size_t)r*HDP + koff);
            cp16(smaddr(&vth[r*KS + koff]), vph + (size_t)r*(SEQ/2) + koff);
            cp16(smaddr(&vtl[r*KS + koff]), vpl + (size_t)r*(SEQ/2) + koff);
        }
        CP_WAIT_ALL();
        __syncthreads();

        #pragma unroll
        for (int sub=0; sub<2; sub++){
            const int nb = nb2*2 + sub;

            // QK^T: 16 x 32, k=64 (4 k16 steps x 3 split-MMAs)
            float cf[4][4];
            #pragma unroll
            for (int nf=0; nf<4; nf++){
                #pragma unroll
                for (int e=0; e<4; e++) cf[nf][e]=0.f;
                int n = sub*32 + nf*8 + g;
                #pragma unroll
                for (int kf=0; kf<4; kf++){
                    uint32_t b0h = kh[n*KS + kf*8 + q], b1h = kh[n*KS + kf*8 + q+4];
                    uint32_t b0l = kl[n*KS + kf*8 + q], b1l = kl[n*KS + kf*8 + q+4];
                    mma_f16(cf[nf], qah[kf][0],qah[kf][1],qah[kf][2],qah[kf][3], b0h,b1h);
                    mma_f16(cf[nf], qah[kf][0],qah[kf][1],qah[kf][2],qah[kf][3], b0l,b1l);
                    mma_f16(cf[nf], qal[kf][0],qal[kf][1],qal[kf][2],qal[kf][3], b0h,b1h);
                }
            }

            // Pointwise: decay, sigmoid, w = rem * beta; split w into hi/lo
            float sw0=0.f, sw1=0.f, mx0=-INFINITY, mx1=-INFINITY;
            #pragma unroll
            for (int nf=0; nf<4; nf++){
                int colk = nf*8 + 2*q;
                float sk0 = (float)(nb*32 + colk);
                float sk1 = sk0 + 1.f;
                {
                    float raw0 = cf[nf][0] - lam*fabsf(sq0 - sk0);
                    float raw1 = cf[nf][1] - lam*fabsf(sq0 - sk1);
                    mx0 = fmaxf(mx0, fmaxf(raw0, raw1));
                    float cl0 = fminf(fmaxf(raw0, -20.f), 20.f);
                    float cl1 = fminf(fmaxf(raw1, -20.f), 20.f);
                    float w0 = rem0 / (1.f + __expf(-cl0));
                    float w1 = rem0 / (1.f + __expf(-cl1));
                    sw0 += w0 + w1;
                    uint32_t hi, lo;
                    split_pair(w0, w1, hi, lo);
                    wsh[rw0*QS + nf*4 + q] = hi;
                    wsl[rw0*QS + nf*4 + q] = lo;
                }
                {
                    float raw0 = cf[nf][2] - lam*fabsf(sq1 - sk0);
                    float raw1 = cf[nf][3] - lam*fabsf(sq1 - sk1);
                    mx1 = fmaxf(mx1, fmaxf(raw0, raw1));
                    float cl0 = fminf(fmaxf(raw0, -20.f), 20.f);
                    float cl1 = fminf(fmaxf(raw1, -20.f), 20.f);
                    float w0 = rem1 / (1.f + __expf(-cl0));
                    float w1 = rem1 / (1.f + __expf(-cl1));
                    sw1 += w0 + w1;
                    uint32_t hi, lo;
                    split_pair(w0, w1, hi, lo);
                    wsh[(rw0+8)*QS + nf*4 + q] = hi;
                    wsl[(rw0+8)*QS + nf*4 + q] = lo;
                }
            }
            #pragma unroll
            for (int ofs=2; ofs>0; ofs>>=1){
                sw0 += __shfl_xor_sync(0xffffffffu, sw0, ofs);
                sw1 += __shfl_xor_sync(0xffffffffu, sw1, ofs);
                mx0  = fmaxf(mx0, __shfl_xor_sync(0xffffffffu, mx0, ofs));
                mx1  = fmaxf(mx1, __shfl_xor_sync(0xffffffffu, mx1, ofs));
            }
            {
                float mn = fmaxf(mi0, mx0);
                li0 = li0*exp2f(mi0-mn) + sw0; mi0 = mn;
                rem0 = fmaxf(rem0*(1.f - sw0), 1e-6f);
            }
            {
                float mn = fmaxf(mi1, mx1);
                li1 = li1*exp2f(mi1-mn) + sw1; mi1 = mn;
                rem1 = fmaxf(rem1*(1.f - sw1), 1e-6f);
            }
            __syncwarp();

            // PV: acc(16 x 64) += w(16 x 32keys) @ V(32keys x 64)
            #pragma unroll
            for (int kf=0; kf<2; kf++){
                uint32_t a0h = wsh[(rw0  )*QS + kf*8 + q  ];
                uint32_t a1h = wsh[(rw0+8)*QS + kf*8 + q  ];
                uint32_t a2h = wsh[(rw0  )*QS + kf*8 + q+4];
                uint32_t a3h = wsh[(rw0+8)*QS + kf*8 + q+4];
                uint32_t a0l = wsl[(rw0  )*QS + kf*8 + q  ];
                uint32_t a1l = wsl[(rw0+8)*QS + kf*8 + q  ];
                uint32_t a2l = wsl[(rw0  )*QS + kf*8 + q+4];
                uint32_t a3l = wsl[(rw0+8)*QS + kf*8 + q+4];
                #pragma unroll
                for (int nf=0; nf<8; nf++){
                    int n = nf*8 + g;
                    uint32_t b0h = vth[n*KS + sub*16 + kf*8 + q], b1h = vth[n*KS + sub*16 + kf*8 + q+4];
                    uint32_t b0l = vtl[n*KS + sub*16 + kf*8 + q], b1l = vtl[n*KS + sub*16 + kf*8 + q+4];
                    mma_f16(acc[nf], a0h,a1h,a2h,a3h, b0h,b1h);
                    mma_f16(acc[nf], a0h,a1h,a2h,a3h, b0l,b1l);
                    mma_f16(acc[nf], a0l,a1l,a2l,a3l, b0h,b1h);
                }
            }
        }
    }

    // Epilogue: normalize and store split O
    const float inv0 = 1.f / fmaxf(li0, 1e-6f);
    const float inv1 = 1.f / fmaxf(li1, 1e-6f);
    uint32_t* poh = g_oh + ((size_t)bh*SEQ + m0 + 16*w)*HDP;
    uint32_t* pol = g_ol + ((size_t)bh*SEQ + m0 + 16*w)*HDP;
    #pragma unroll
    for (int nf=0; nf<8; nf++){
        int dp = nf*4 + q;
        uint32_t hi, lo;
        split_pair(acc[nf][0]*inv0, acc[nf][1]*inv0, hi, lo);
        poh[(size_t)(g  )*HDP + dp] = hi; pol[(size_t)(g  )*HDP + dp] = lo;
        split_pair(acc[nf][2]*inv1, acc[nf][3]*inv1, hi, lo);
        poh[(size_t)(g+8)*HDP + dp] = hi; pol[(size_t)(g+8)*HDP + dp] = lo;
    }
}

// ---------------------------------------------------------------------------
// Output projection: y = ctx @ Wo^T + bo. grid=(128,12), 256 threads.
// BM=128, BN=64, BK=32dp, cp.async coalesced loads.
// ---------------------------------------------------------------------------
__global__ __launch_bounds__(256) void out_kernel(
    const float* __restrict__ bo, float* __restrict__ y)
{
    extern __shared__ uint32_t smem[];
    uint32_t* xsh  = smem;
    uint32_t* xsl  = xsh  + 128*KS;
    uint32_t* wsh_ = xsl  + 128*KS;
    uint32_t* wsl_ = wsh_ + 64*KS;

    const int row0 = blockIdx.x * 128;
    const int cb   = blockIdx.y;
    const int tid  = threadIdx.x;
    const int w    = tid >> 5, lane = tid & 31;
    const int g    = lane >> 2, q = lane & 3;
    const int warpm = w >> 1, warpn = w & 1;

    float c[2][4][4];
    #pragma unroll
    for (int mf=0; mf<2; mf++)
        #pragma unroll
        for (int nf=0; nf<4; nf++)
            #pragma unroll
            for (int e=0; e<4; e++) c[mf][nf][e]=0.f;

    const int lrow = tid >> 3;
    const int koff = (tid & 7) * 4;
    const uint32_t* wbh = g_wh + (size_t)(3*HIDN + cb*64)*XDP;
    const uint32_t* wbl = g_wl + (size_t)(3*HIDN + cb*64)*XDP;

    for (int k0 = 0; k0 < XDP; k0 += 32) {
        const int hh = k0 >> 5;          // k-chunk == one head
        __syncthreads();
        #pragma unroll
        for (int i=0; i<4; i++){
            int r = lrow + 32*i;
            int grow = row0 + r;
            int b_ = grow >> 10, s_ = grow & 1023;
            size_t xi = ((size_t)(b_*NH + hh)*SEQ + s_)*HDP + koff;
            cp16(smaddr(&xsh[r*KS + koff]), g_oh + xi);
            cp16(smaddr(&xsl[r*KS + koff]), g_ol + xi);
        }
        #pragma unroll
        for (int i=0; i<2; i++){
            int r = lrow + 32*i;
            cp16(smaddr(&wsh_[r*KS + koff]), wbh + (size_t)r*XDP + k0 + koff);
            cp16(smaddr(&wsl_[r*KS + koff]), wbl + (size_t)r*XDP + k0 + koff);
        }
        CP_WAIT_ALL();
        __syncthreads();
        #pragma unroll
        for (int kf=0; kf<4; kf++){
            uint32_t ah[2][4], al[2][4];
            #pragma unroll
            for (int mf=0; mf<2; mf++){
                int r = warpm*32 + mf*16 + g;
                ah[mf][0]=xsh[(r  )*KS + kf*8 + q  ]; ah[mf][1]=xsh[(r+8)*KS + kf*8 + q  ];
                ah[mf][2]=xsh[(r  )*KS + kf*8 + q+4]; ah[mf][3]=xsh[(r+8)*KS + kf*8 + q+4];
                al[mf][0]=xsl[(r  )*KS + kf*8 + q  ]; al[mf][1]=xsl[(r+8)*KS + kf*8 + q  ];
                al[mf][2]=xsl[(r  )*KS + kf*8 + q+4]; al[mf][3]=xsl[(r+8)*KS + kf*8 + q+4];
            }
            #pragma unroll
            for (int nf=0; nf<4; nf++){
                int n = warpn*32 + nf*8 + g;
                uint32_t bh0=wsh_[n*KS + kf*8 + q], bh1=wsh_[n*KS + kf*8 + q+4];
                uint32_t bl0=wsl_[n*KS + kf*8 + q], bl1=wsl_[n*KS + kf*8 + q+4];
                #pragma unroll
                for (int mf=0; mf<2; mf++){
                    mma_f16(c[mf][nf], ah[mf][0],ah[mf][1],ah[mf][2],ah[mf][3], bh0,bh1);
                    mma_f16(c[mf][nf], ah[mf][0],ah[mf][1],ah[mf][2],ah[mf][3], bl0,bl1);
                    mma_f16(c[mf][nf], al[mf][0],al[mf][1],al[mf][2],al[mf][3], bh0,bh1);
                }
            }
        }
    }

    #pragma unroll
    for (int nf=0; nf<4; nf++){
        int col = cb*64 + warpn*32 + nf*8 + 2*q;
        float b0 = bo[col], b1 = bo[col+1];
        #pragma unroll
        for (int mf=0; mf<2; mf++){
            #pragma unroll
            for (int half=0; half<2; half++){
                int row = row0 + warpm*32 + mf*16 + g + half*8;
                *(float2*)(y + (size_t)row*HIDN + col) =
                    make_float2(c[mf][nf][half*2+0] + b0,
                                c[mf][nf][half*2+1] + b1);
            }
        }
    }
}

// ---------------------------------------------------------------------------
extern "C" void kernel_launch(void* const* d_in, const int* in_sizes, int n_in,
                              void* d_out, int out_size)
{
    const float* x    = (const float*)d_in[0];
    const float* Wq   = (const float*)d_in[1];
    const float* bq   = (const float*)d_in[2];
    const float* Wk   = (const float*)d_in[3];
    const float* bk   = (const float*)d_in[4];
    const float* Wv   = (const float*)d_in[5];
    const float* bv   = (const float*)d_in[6];
    const float* Wo   = (const float*)d_in[7];
    const float* bo   = (const float*)d_in[8];
    const float* lam  = (const float*)d_in[9];
    const float* cosc = (const float*)d_in[10];
    const float* sinc = (const float*)d_in[11];
    float* y = (float*)d_out;

    static int configured = 0;
    if (!configured){
        cudaFuncSetAttribute(qkv_kernel, cudaFuncAttributeMaxDynamicSharedMemorySize, QKV_SMEM);
        cudaFuncSetAttribute(attn_kernel, cudaFuncAttributeMaxDynamicSharedMemorySize, ATTN_SMEM);
        cudaFuncSetAttribute(out_kernel, cudaFuncAttributeMaxDynamicSharedMemorySize, QKV_SMEM);
        configured = 1;
    }

    const int nf4_x = BDIM*SEQ*HIDN/4;
    const int nf4_w = HIDN*HIDN/4;
    split_conv<<<(nf4_x+255)/256, 256>>>(x,  0, nf4_x);
    split_conv<<<(nf4_w+255)/256, 256>>>(Wq, 1, nf4_w);
    split_conv<<<(nf4_w+255)/256, 256>>>(Wk, 2, nf4_w);
    split_conv<<<(nf4_w+255)/256, 256>>>(Wv, 3, nf4_w);
    split_conv<<<(nf4_w+255)/256, 256>>>(Wo, 4, nf4_w);

    dim3 g1(BDIM*SEQ/128, NH, 3);
    qkv_kernel<<<g1, 256, QKV_SMEM>>>(bq, bk, bv, cosc, sinc);

    dim3 gt(SEQ/64, NBH);
    vtrans_kernel<<<gt, 256>>>();

    dim3 g2(SEQ/128, NBH);
    attn_kernel<<<g2, 256, ATTN_SMEM>>>(lam);

    dim3 g3(BDIM*SEQ/128, NH);
    out_kernel<<<g3, 256, QKV_SMEM>>>(bo, y);
}